// round 11
// baseline (speedup 1.0000x reference)
#include <cuda_runtime.h>

#define Tt 2048
#define Bb 512
#define Cc 8
#define Hh 20
#define GRP 4
#define NG (Tt / GRP)   // 512 groups
#define NI (NG + 3)     // pipeline fill: A lags 1 group, B(u) 2, C 3

typedef unsigned long long u64;

__device__ __forceinline__ u64 pack2(float a, float b) {
    u64 r; asm("mov.b64 %0, {%1, %2};" : "=l"(r) : "f"(a), "f"(b)); return r;
}
__device__ __forceinline__ void unpack2(u64 v, float &a, float &b) {
    asm("mov.b64 {%0, %1}, %2;" : "=f"(a), "=f"(b) : "l"(v));
}
// packed dual-FMA: d.x += a.x*b.x ; d.y += a.y*b.y
__device__ __forceinline__ void ffma2(u64 &d, u64 a, u64 b) {
    asm("fma.rn.f32x2 %0, %1, %2, %0;" : "+l"(d) : "l"(a), "l"(b));
}
__device__ __forceinline__ float hadd2(u64 v) {
    float a, b; unpack2(v, a, b); return a + b;
}
__device__ __forceinline__ float tanhfast(float x) {
    float y; asm("tanh.approx.f32 %0, %1;" : "=f"(y) : "f"(x)); return y;
}
// sigmoid with the inner 0.5 pre-folded into weights/bias
__device__ __forceinline__ float sigmfolded(float halfz) {
    return fmaf(tanhfast(halfz), 0.5f, 0.5f);
}

// 3 warps per batch (block = 4 batches x 3 roles = 384 threads, 12 warps/SM,
// 3 warps per SMSP = roles A,B,C of the same batch):
//  A: layer-1 recurrence only (Whh0@h1 + cell), reads gx ring.
//  B: chain-free feed-forward: gx[t]=b0+Wih0@x[t] (1 group AHEAD of A) and
//     u[t]=b1+Wih1@h1[t] (1 group BEHIND A). Pure latency filler.
//  C: layer-2 recurrence only (u + Whh1@h2 + cell), 1 group behind B's u.
// One bar.sync(1+bl, 96) per 4-step group; recurrent chains stay warp-local.
__global__ void __launch_bounds__(384, 1) lstm2_kernel(
    const float* __restrict__ x,
    const float* __restrict__ Wih0, const float* __restrict__ Whh0,
    const float* __restrict__ bih0, const float* __restrict__ bhh0,
    const float* __restrict__ Wih1, const float* __restrict__ Whh1,
    const float* __restrict__ bih1, const float* __restrict__ bhh1,
    float* __restrict__ out)
{
    __shared__ __align__(16) float4 gxring[4][8][32];   // [bl][slot][lane]
    __shared__ __align__(16) float4 uring[4][8][32];
    __shared__ __align__(16) float  h1ring[4][8][24];
    __shared__ __align__(16) float  h2buf[4][24];

    const int tid   = threadIdx.x;
    const int w     = tid >> 5;
    const int lane  = tid & 31;
    const int bl    = w & 3;        // batch-local index == SMSP index
    const int role  = w >> 2;       // 0=A, 1=B, 2=C
    const int batch = blockIdx.x * 4 + bl;
    const int barid = 1 + bl;

    if (role == 0) {
        // ---------------- A: layer-1 recurrence ----------------
        u64 wh[4][10];
        if (lane < Hh) {
            #pragma unroll
            for (int g = 0; g < 4; g++) {
                const float sc = (g == 2) ? 1.0f : 0.5f;
                const float* rh = Whh0 + (g * Hh + lane) * Hh;
                #pragma unroll
                for (int kp = 0; kp < 10; kp++)
                    wh[g][kp] = pack2(sc * rh[2*kp], sc * rh[2*kp+1]);
            }
        }
        u64 hp[10];
        #pragma unroll
        for (int kp = 0; kp < 10; kp++) hp[kp] = 0ull;
        float c1 = 0.f;

        #pragma unroll 1
        for (int i = 0; i < NI; i++) {
            if (i >= 1 && i <= NG) {
                const int t0 = (i - 1) * GRP;
                // hoist all 4 gx loads off the recurrence chain
                float4 gxa[4];
                #pragma unroll
                for (int s = 0; s < GRP; s++)
                    gxa[s] = gxring[bl][(t0 + s) & 7][lane];
                #pragma unroll
                for (int s = 0; s < GRP; s++) {
                    u64 a0 = pack2(gxa[s].x, 0.f);
                    u64 a1 = pack2(gxa[s].y, 0.f);
                    u64 a2 = pack2(gxa[s].z, 0.f);
                    u64 a3 = pack2(gxa[s].w, 0.f);
                    #pragma unroll
                    for (int kp = 0; kp < 10; kp++) {
                        u64 v = hp[kp];
                        ffma2(a0, wh[0][kp], v); ffma2(a1, wh[1][kp], v);
                        ffma2(a2, wh[2][kp], v); ffma2(a3, wh[3][kp], v);
                    }
                    float ia = sigmfolded(hadd2(a0));
                    float fa = sigmfolded(hadd2(a1));
                    float ga = tanhfast(hadd2(a2));
                    float oa = sigmfolded(hadd2(a3));
                    c1 = fmaf(fa, c1, ia * ga);
                    float h1 = oa * tanhfast(c1);
                    if (lane < Hh) h1ring[bl][(t0 + s) & 7][lane] = h1;
                    __syncwarp();
                    const u64* rp = (const u64*)&h1ring[bl][(t0 + s) & 7][0];
                    #pragma unroll
                    for (int kp = 0; kp < 10; kp++) hp[kp] = rp[kp];
                }
            }
            asm volatile("bar.sync %0, 96;" :: "r"(barid) : "memory");
        }
    } else if (role == 1) {
        // ---------------- B: chain-free feed-forward ----------------
        u64 wx[4][4], w1[4][10], binit0[4], binit1[4];
        if (lane < Hh) {
            #pragma unroll
            for (int g = 0; g < 4; g++) {
                const float sc = (g == 2) ? 1.0f : 0.5f;
                const int row = g * Hh + lane;
                const float* rx = Wih0 + row * Cc;
                #pragma unroll
                for (int kp = 0; kp < 4; kp++)
                    wx[g][kp] = pack2(sc * rx[2*kp], sc * rx[2*kp+1]);
                const float* r1 = Wih1 + row * Hh;
                #pragma unroll
                for (int kp = 0; kp < 10; kp++)
                    w1[g][kp] = pack2(sc * r1[2*kp], sc * r1[2*kp+1]);
                binit0[g] = pack2(sc * (bih0[row] + bhh0[row]), 0.f);
                binit1[g] = pack2(sc * (bih1[row] + bhh1[row]), 0.f);
            }
        }
        // rolling x pipeline: gx t's are globally consecutive across intervals
        const ulonglong2* xb = ((const ulonglong2*)x) + (size_t)batch * 2;
        ulonglong2 x0a = xb[0],    x0b = xb[1];        // row t
        ulonglong2 x1a = xb[1024], x1b = xb[1025];     // row t+1

        #pragma unroll 1
        for (int i = 0; i < NI; i++) {
            if (i < NG) {
                const int t0 = i * GRP;
                #pragma unroll
                for (int s = 0; s < GRP; s++) {
                    const int t = t0 + s;
                    u64 xv0 = x0a.x, xv1 = x0a.y, xv2 = x0b.x, xv3 = x0b.y;
                    x0a = x1a; x0b = x1b;
                    if (t + 2 < Tt) {
                        const ulonglong2* xq = xb + (size_t)(t + 2) * 1024;
                        x1a = xq[0]; x1b = xq[1];
                    }
                    u64 a0 = binit0[0], a1 = binit0[1], a2 = binit0[2], a3 = binit0[3];
                    ffma2(a0, wx[0][0], xv0); ffma2(a1, wx[1][0], xv0);
                    ffma2(a2, wx[2][0], xv0); ffma2(a3, wx[3][0], xv0);
                    ffma2(a0, wx[0][1], xv1); ffma2(a1, wx[1][1], xv1);
                    ffma2(a2, wx[2][1], xv1); ffma2(a3, wx[3][1], xv1);
                    ffma2(a0, wx[0][2], xv2); ffma2(a1, wx[1][2], xv2);
                    ffma2(a2, wx[2][2], xv2); ffma2(a3, wx[3][2], xv2);
                    ffma2(a0, wx[0][3], xv3); ffma2(a1, wx[1][3], xv3);
                    ffma2(a2, wx[2][3], xv3); ffma2(a3, wx[3][3], xv3);
                    float4 gxv = make_float4(hadd2(a0), hadd2(a1),
                                             hadd2(a2), hadd2(a3));
                    if (lane < Hh) gxring[bl][t & 7][lane] = gxv;
                }
            }
            if (i >= 2 && i < NG + 2) {
                const int t0 = (i - 2) * GRP;
                #pragma unroll
                for (int s = 0; s < GRP; s++) {
                    const int t = t0 + s;
                    const u64* h1p = (const u64*)&h1ring[bl][t & 7][0];
                    u64 a0 = binit1[0], a1 = binit1[1], a2 = binit1[2], a3 = binit1[3];
                    #pragma unroll
                    for (int kp = 0; kp < 10; kp++) {
                        u64 v = h1p[kp];
                        ffma2(a0, w1[0][kp], v); ffma2(a1, w1[1][kp], v);
                        ffma2(a2, w1[2][kp], v); ffma2(a3, w1[3][kp], v);
                    }
                    float4 uv = make_float4(hadd2(a0), hadd2(a1),
                                            hadd2(a2), hadd2(a3));
                    if (lane < Hh) uring[bl][t & 7][lane] = uv;
                }
            }
            asm volatile("bar.sync %0, 96;" :: "r"(barid) : "memory");
        }
    } else {
        // ---------------- C: layer-2 recurrence ----------------
        u64 w2[4][10];
        if (lane < Hh) {
            #pragma unroll
            for (int g = 0; g < 4; g++) {
                const float sc = (g == 2) ? 1.0f : 0.5f;
                const float* r2 = Whh1 + (g * Hh + lane) * Hh;
                #pragma unroll
                for (int kp = 0; kp < 10; kp++)
                    w2[g][kp] = pack2(sc * r2[2*kp], sc * r2[2*kp+1]);
            }
        }
        u64 h2p[10];
        #pragma unroll
        for (int kp = 0; kp < 10; kp++) h2p[kp] = 0ull;
        float c2 = 0.f;
        float* outp = out + (size_t)batch * Hh + lane;

        #pragma unroll 1
        for (int i = 0; i < NI; i++) {
            if (i >= 3) {
                const int t0 = (i - 3) * GRP;
                // hoist all 4 u loads off the recurrence chain
                float4 ua[4];
                #pragma unroll
                for (int s = 0; s < GRP; s++)
                    ua[s] = uring[bl][(t0 + s) & 7][lane];
                #pragma unroll
                for (int s = 0; s < GRP; s++) {
                    u64 a0 = pack2(ua[s].x, 0.f);
                    u64 a1 = pack2(ua[s].y, 0.f);
                    u64 a2 = pack2(ua[s].z, 0.f);
                    u64 a3 = pack2(ua[s].w, 0.f);
                    #pragma unroll
                    for (int kp = 0; kp < 10; kp++) {
                        u64 v = h2p[kp];
                        ffma2(a0, w2[0][kp], v); ffma2(a1, w2[1][kp], v);
                        ffma2(a2, w2[2][kp], v); ffma2(a3, w2[3][kp], v);
                    }
                    float ia = sigmfolded(hadd2(a0));
                    float fa = sigmfolded(hadd2(a1));
                    float ga = tanhfast(hadd2(a2));
                    float oa = sigmfolded(hadd2(a3));
                    c2 = fmaf(fa, c2, ia * ga);
                    float h2 = oa * tanhfast(c2);
                    if (lane < Hh) {
                        *outp = h2;
                        h2buf[bl][lane] = h2;
                    }
                    outp += Bb * Hh;
                    __syncwarp();
                    const u64* rp2 = (const u64*)&h2buf[bl][0];
                    #pragma unroll
                    for (int kp = 0; kp < 10; kp++) h2p[kp] = rp2[kp];
                }
            }
            asm volatile("bar.sync %0, 96;" :: "r"(barid) : "memory");
        }
    }
}

extern "C" void kernel_launch(void* const* d_in, const int* in_sizes, int n_in,
                              void* d_out, int out_size) {
    lstm2_kernel<<<Bb / 4, 384>>>(
        (const float*)d_in[0],
        (const float*)d_in[1], (const float*)d_in[2],
        (const float*)d_in[3], (const float*)d_in[4],
        (const float*)d_in[5], (const float*)d_in[6],
        (const float*)d_in[7], (const float*)d_in[8],
        (float*)d_out);
}

// round 12
// speedup vs baseline: 1.6508x; 1.6508x over previous
#include <cuda_runtime.h>

#define Tt 2048
#define Bb 512
#define Cc 8
#define Hh 20
#define GRP 4
#define RING 8

typedef unsigned long long u64;

__device__ __forceinline__ u64 pack2(float a, float b) {
    u64 r; asm("mov.b64 %0, {%1, %2};" : "=l"(r) : "f"(a), "f"(b)); return r;
}
__device__ __forceinline__ void unpack2(u64 v, float &a, float &b) {
    asm("mov.b64 {%0, %1}, %2;" : "=f"(a), "=f"(b) : "l"(v));
}
// packed dual-FMA: d.x += a.x*b.x ; d.y += a.y*b.y
__device__ __forceinline__ void ffma2(u64 &d, u64 a, u64 b) {
    asm("fma.rn.f32x2 %0, %1, %2, %0;" : "+l"(d) : "l"(a), "l"(b));
}
__device__ __forceinline__ float hadd2(u64 v) {
    float a, b; unpack2(v, a, b); return a + b;
}
__device__ __forceinline__ float tanhfast(float x) {
    float y; asm("tanh.approx.f32 %0, %1;" : "=f"(y) : "f"(x)); return y;
}
// sigmoid with the inner 0.5 pre-folded into weights/bias:
// sigmoid(z) = 0.5*tanh(0.5*z) + 0.5 ; acc already equals 0.5*z.
__device__ __forceinline__ float sigmfolded(float halfz) {
    return fmaf(tanhfast(halfz), 0.5f, 0.5f);
}

// Champion architecture: 2 warps per batch, role 0 = layer-1 producer,
// role 1 = layer-2 consumer one GROUP (4 steps) behind via depth-8 smem ring,
// one named barrier per 4 steps, weights in registers (sigmoid 0.5 folded).
// R12 delta (L2 branch only): the next step's input-GEMV
// n = bias1 + Wih1 @ h1[t+1] is staged DURING the current step's
// activation/cell stall, so the recurrent chain starts from a ready
// accumulator. Summation order identical to champion.
__global__ void __launch_bounds__(256, 1) lstm2_kernel(
    const float* __restrict__ x,
    const float* __restrict__ Wih0, const float* __restrict__ Whh0,
    const float* __restrict__ bih0, const float* __restrict__ bhh0,
    const float* __restrict__ Wih1, const float* __restrict__ Whh1,
    const float* __restrict__ bih1, const float* __restrict__ bhh1,
    float* __restrict__ out)
{
    __shared__ __align__(16) float h1ring[4][RING][24];
    __shared__ __align__(16) float h2buf[4][24];

    const int tid   = threadIdx.x;
    const int w     = tid >> 5;
    const int lane  = tid & 31;
    const int pair  = w >> 1;
    // flip roles on pairs 2,3 so each SMSP hosts one L1 + one L2 warp
    const int role  = (w & 1) ^ ((w >> 2) & 1);
    const int batch = blockIdx.x * 4 + pair;
    const int barid = pair + 1;

    if (role == 0) {
        // ---------------- layer 1 (producer) — byte-identical to champion ----
        u64 wx[4][4], wh[4][10], binit[4];
        if (lane < Hh) {
            #pragma unroll
            for (int g = 0; g < 4; g++) {
                const float sc = (g == 2) ? 1.0f : 0.5f;   // fold sigmoid 0.5
                const int row = g * Hh + lane;              // gate order i,f,g,o
                const float* rx = Wih0 + row * Cc;
                #pragma unroll
                for (int kp = 0; kp < 4; kp++)
                    wx[g][kp] = pack2(sc * rx[2*kp], sc * rx[2*kp+1]);
                const float* rh = Whh0 + row * Hh;
                #pragma unroll
                for (int kp = 0; kp < 10; kp++)
                    wh[g][kp] = pack2(sc * rh[2*kp], sc * rh[2*kp+1]);
                binit[g] = pack2(sc * (bih0[row] + bhh0[row]), 0.f);
            }
        }
        // x prefetch pipeline, depth 2 (uniform LDG.128 pairs, broadcast)
        const ulonglong2* xb = ((const ulonglong2*)x) + (size_t)batch * 2;
        ulonglong2 x0a = xb[0],    x0b = xb[1];        // t = 0
        ulonglong2 x1a = xb[1024], x1b = xb[1025];     // t = 1
        u64 hp[10];
        #pragma unroll
        for (int kp = 0; kp < 10; kp++) hp[kp] = 0ull;
        float c1 = 0.f;

        #pragma unroll 1
        for (int p = 0; p < Tt / GRP; p++) {
            #pragma unroll
            for (int s = 0; s < GRP; s++) {
                const int t = p * GRP + s;
                u64 xv0 = x0a.x, xv1 = x0a.y, xv2 = x0b.x, xv3 = x0b.y;
                x0a = x1a; x0b = x1b;
                if (t + 2 < Tt) {                      // prefetch t+2
                    const ulonglong2* xq = xb + (size_t)(t + 2) * 1024;
                    x1a = xq[0]; x1b = xq[1];
                }
                u64 a0 = binit[0], a1 = binit[1], a2 = binit[2], a3 = binit[3];
                ffma2(a0, wx[0][0], xv0); ffma2(a1, wx[1][0], xv0);
                ffma2(a2, wx[2][0], xv0); ffma2(a3, wx[3][0], xv0);
                ffma2(a0, wx[0][1], xv1); ffma2(a1, wx[1][1], xv1);
                ffma2(a2, wx[2][1], xv1); ffma2(a3, wx[3][1], xv1);
                ffma2(a0, wx[0][2], xv2); ffma2(a1, wx[1][2], xv2);
                ffma2(a2, wx[2][2], xv2); ffma2(a3, wx[3][2], xv2);
                ffma2(a0, wx[0][3], xv3); ffma2(a1, wx[1][3], xv3);
                ffma2(a2, wx[2][3], xv3); ffma2(a3, wx[3][3], xv3);
                #pragma unroll
                for (int j = 0; j < 5; j++) {
                    u64 v0 = hp[2*j], v1 = hp[2*j+1];
                    ffma2(a0, wh[0][2*j],   v0); ffma2(a1, wh[1][2*j],   v0);
                    ffma2(a2, wh[2][2*j],   v0); ffma2(a3, wh[3][2*j],   v0);
                    ffma2(a0, wh[0][2*j+1], v1); ffma2(a1, wh[1][2*j+1], v1);
                    ffma2(a2, wh[2][2*j+1], v1); ffma2(a3, wh[3][2*j+1], v1);
                }
                float ia = sigmfolded(hadd2(a0));
                float fa = sigmfolded(hadd2(a1));
                float ga = tanhfast(hadd2(a2));
                float oa = sigmfolded(hadd2(a3));
                c1 = fmaf(fa, c1, ia * ga);
                float h1 = oa * tanhfast(c1);
                if (lane < Hh) h1ring[pair][t & (RING - 1)][lane] = h1;
                __syncwarp();
                // prefetch own broadcast pairs for next step (off critical path)
                const u64* rp = (const u64*)&h1ring[pair][t & (RING - 1)][0];
                #pragma unroll
                for (int kp = 0; kp < 10; kp++) hp[kp] = rp[kp];
            }
            asm volatile("bar.sync %0, 64;" :: "r"(barid) : "memory");
        }
    } else {
        // ---------------- layer 2 (consumer, one group behind) ----------------
        u64 w1[4][10], w2[4][10], binit[4];
        if (lane < Hh) {
            #pragma unroll
            for (int g = 0; g < 4; g++) {
                const float sc = (g == 2) ? 1.0f : 0.5f;   // fold sigmoid 0.5
                const int row = g * Hh + lane;
                const float* r1 = Wih1 + row * Hh;
                const float* r2 = Whh1 + row * Hh;
                #pragma unroll
                for (int kp = 0; kp < 10; kp++) {
                    w1[g][kp] = pack2(sc * r1[2*kp], sc * r1[2*kp+1]);
                    w2[g][kp] = pack2(sc * r2[2*kp], sc * r2[2*kp+1]);
                }
                binit[g] = pack2(sc * (bih1[row] + bhh1[row]), 0.f);
            }
        }
        u64 h2p[10];
        #pragma unroll
        for (int kp = 0; kp < 10; kp++) h2p[kp] = 0ull;
        float c2 = 0.f;

        #pragma unroll 1
        for (int p = 0; p < Tt / GRP; p++) {
            asm volatile("bar.sync %0, 64;" :: "r"(barid) : "memory");
            // group prologue: stage n = bias1 + Wih1 @ h1[t0]
            u64 n0, n1, n2, n3;
            {
                const u64* rp = (const u64*)&h1ring[pair][(p * GRP) & (RING - 1)][0];
                n0 = binit[0]; n1 = binit[1]; n2 = binit[2]; n3 = binit[3];
                #pragma unroll
                for (int kp = 0; kp < 10; kp++) {
                    u64 v = rp[kp];
                    ffma2(n0, w1[0][kp], v); ffma2(n1, w1[1][kp], v);
                    ffma2(n2, w1[2][kp], v); ffma2(n3, w1[3][kp], v);
                }
            }
            #pragma unroll
            for (int s = 0; s < GRP; s++) {
                const int t = p * GRP + s;
                // recurrent part: start from staged input-GEMV accumulators
                u64 a0 = n0, a1 = n1, a2 = n2, a3 = n3;
                #pragma unroll
                for (int j = 0; j < 5; j++) {
                    u64 v0 = h2p[2*j], v1 = h2p[2*j+1];
                    ffma2(a0, w2[0][2*j],   v0); ffma2(a1, w2[1][2*j],   v0);
                    ffma2(a2, w2[2][2*j],   v0); ffma2(a3, w2[3][2*j],   v0);
                    ffma2(a0, w2[0][2*j+1], v1); ffma2(a1, w2[1][2*j+1], v1);
                    ffma2(a2, w2[2][2*j+1], v1); ffma2(a3, w2[3][2*j+1], v1);
                }
                // stage next step's input-GEMV (independent of the chain above;
                // h1[t+1] is already in the ring, written pre-barrier) — this
                // fills the activation/cell stall below.
                if (s < GRP - 1) {
                    const u64* rp = (const u64*)&h1ring[pair][(t + 1) & (RING - 1)][0];
                    n0 = binit[0]; n1 = binit[1]; n2 = binit[2]; n3 = binit[3];
                    #pragma unroll
                    for (int kp = 0; kp < 10; kp++) {
                        u64 v = rp[kp];
                        ffma2(n0, w1[0][kp], v); ffma2(n1, w1[1][kp], v);
                        ffma2(n2, w1[2][kp], v); ffma2(n3, w1[3][kp], v);
                    }
                }
                float ia = sigmfolded(hadd2(a0));
                float fa = sigmfolded(hadd2(a1));
                float ga = tanhfast(hadd2(a2));
                float oa = sigmfolded(hadd2(a3));
                c2 = fmaf(fa, c2, ia * ga);
                float h2 = oa * tanhfast(c2);
                if (lane < Hh) {
                    out[(size_t)t * Bb * Hh + batch * Hh + lane] = h2;
                    h2buf[pair][lane] = h2;
                }
                __syncwarp();
                const u64* rp2 = (const u64*)&h2buf[pair][0];
                #pragma unroll
                for (int kp = 0; kp < 10; kp++) h2p[kp] = rp2[kp];
            }
        }
    }
}

extern "C" void kernel_launch(void* const* d_in, const int* in_sizes, int n_in,
                              void* d_out, int out_size) {
    lstm2_kernel<<<Bb / 4, 256>>>(
        (const float*)d_in[0],
        (const float*)d_in[1], (const float*)d_in[2],
        (const float*)d_in[3], (const float*)d_in[4],
        (const float*)d_in[5], (const float*)d_in[6],
        (const float*)d_in[7], (const float*)d_in[8],
        (float*)d_out);
}